// round 1
// baseline (speedup 1.0000x reference)
#include <cuda_runtime.h>
#include <cstdint>

#define MAX_NODES 100000
#define D 64

// ---------------- scratch (device globals: no allocation allowed) ----------
__device__ float g_pre_dst[(size_t)MAX_NODES * D];  // x@W1a + (u@W1d + b1)[batch]
__device__ float g_pre_src[(size_t)MAX_NODES * D];  // x@W1b
__device__ float g_agg[(size_t)MAX_NODES * D];      // scatter-sum target
__device__ float g_ugb[16 * D];                     // u@W1d + b1 per graph
__device__ float g_uc2[16 * D];                     // u@W2c + b2 per graph

// ---------------- packed f32x2 helpers (Blackwell FFMA2) -------------------
__device__ __forceinline__ unsigned long long fma2(unsigned long long a,
                                                   unsigned long long b,
                                                   unsigned long long c) {
    unsigned long long d;
    asm("fma.rn.f32x2 %0, %1, %2, %3;" : "=l"(d) : "l"(a), "l"(b), "l"(c));
    return d;
}
__device__ __forceinline__ unsigned long long pack2(float x, float y) {
    unsigned long long r;
    asm("mov.b64 %0, {%1, %2};" : "=l"(r) : "f"(x), "f"(y));
    return r;
}
__device__ __forceinline__ float2 unpack2(unsigned long long v) {
    float2 r;
    asm("mov.b64 {%0, %1}, %2;" : "=f"(r.x), "=f"(r.y) : "l"(v));
    return r;
}

// ---------------- K0: per-graph precompute ---------------------------------
// ugb[g][j] = b1[j] + sum_k u[g][k] * W1[160+k][j]
// uc2[g][j] = b2[j] + sum_k u[g][k] * W2[128+k][j]
__global__ void glob_pre(const float* __restrict__ u,
                         const float* __restrict__ W1, const float* __restrict__ b1,
                         const float* __restrict__ W2, const float* __restrict__ b2) {
    int j = threadIdx.x;   // 0..63
    int g = threadIdx.y;   // 0..15
    float s1 = b1[j], s2 = b2[j];
#pragma unroll
    for (int k = 0; k < 32; k++) {
        float uv = u[g * 32 + k];
        s1 += uv * W1[(160 + k) * 64 + j];
        s2 += uv * W2[(128 + k) * 64 + j];
    }
    g_ugb[g * 64 + j] = s1;
    g_uc2[g * 64 + j] = s2;
}

// ---------------- zero agg --------------------------------------------------
__global__ void zero_agg(int n4) {
    int i = blockIdx.x * blockDim.x + threadIdx.x;
    if (i < n4) reinterpret_cast<float4*>(g_agg)[i] = make_float4(0.f, 0.f, 0.f, 0.f);
}

// ---------------- dense node GEMM -------------------------------------------
// out[n][0:64] = (relu?)( sum_a A_a[n][0:64] @ W[a*64 : a*64+64][0:64]
//                         + (table ? table[batch[n]][0:64] : 0) )
// Tile: 64 nodes x 64 cols per block, 256 threads, micro-tile 4x4.
__global__ __launch_bounds__(256) void dense_gemm(
    const float* __restrict__ A0, const float* __restrict__ A1,
    const float* __restrict__ W, const float* __restrict__ table,
    const int* __restrict__ batch, float* __restrict__ out,
    int N, int nA, int do_relu) {
    __shared__ float sXT[64][68];   // [k][node], padded
    __shared__ float sW[64][64];    // [k][col]
    const int tid = threadIdx.x;
    const int tn = tid & 15;        // node group (4 nodes)
    const int tj = tid >> 4;        // col group  (4 cols)
    const int node0 = blockIdx.x * 64;

    unsigned long long acc[4][2];
#pragma unroll
    for (int i = 0; i < 4; i++) { acc[i][0] = 0ull; acc[i][1] = 0ull; }

    for (int a = 0; a < nA; a++) {
        const float* __restrict__ A = (a == 0) ? A0 : A1;
        for (int i = tid; i < 4096; i += 256) {
            int r = i >> 6, c = i & 63;
            int n = node0 + r;
            sXT[c][r] = (n < N) ? A[(size_t)n * 64 + c] : 0.f;
        }
        for (int i = tid; i < 4096; i += 256) {
            int k = i >> 6, j = i & 63;
            sW[k][j] = W[(size_t)(a * 64 + k) * 64 + j];
        }
        __syncthreads();
#pragma unroll 8
        for (int k = 0; k < 64; k++) {
            float4 xv = *reinterpret_cast<const float4*>(&sXT[k][tn * 4]);
            ulonglong2 wv = *reinterpret_cast<const ulonglong2*>(&sW[k][tj * 4]);
            unsigned long long xd;
            xd = pack2(xv.x, xv.x);
            acc[0][0] = fma2(xd, wv.x, acc[0][0]); acc[0][1] = fma2(xd, wv.y, acc[0][1]);
            xd = pack2(xv.y, xv.y);
            acc[1][0] = fma2(xd, wv.x, acc[1][0]); acc[1][1] = fma2(xd, wv.y, acc[1][1]);
            xd = pack2(xv.z, xv.z);
            acc[2][0] = fma2(xd, wv.x, acc[2][0]); acc[2][1] = fma2(xd, wv.y, acc[2][1]);
            xd = pack2(xv.w, xv.w);
            acc[3][0] = fma2(xd, wv.x, acc[3][0]); acc[3][1] = fma2(xd, wv.y, acc[3][1]);
        }
        __syncthreads();
    }

#pragma unroll
    for (int nn = 0; nn < 4; nn++) {
        int n = node0 + tn * 4 + nn;
        if (n < N) {
            float2 p0 = unpack2(acc[nn][0]);
            float2 p1 = unpack2(acc[nn][1]);
            float4 o = make_float4(p0.x, p0.y, p1.x, p1.y);
            if (table) {
                int g = __ldg(batch + n);
                float4 tv = *reinterpret_cast<const float4*>(table + g * 64 + tj * 4);
                o.x += tv.x; o.y += tv.y; o.z += tv.z; o.w += tv.w;
            }
            if (do_relu) {
                o.x = fmaxf(o.x, 0.f); o.y = fmaxf(o.y, 0.f);
                o.z = fmaxf(o.z, 0.f); o.w = fmaxf(o.w, 0.f);
            }
            *reinterpret_cast<float4*>(out + (size_t)n * 64 + tj * 4) = o;
        }
    }
}

// ---------------- edge kernel ------------------------------------------------
// One warp per edge. Lane l owns output cols (2l, 2l+1).
// W1c (rows 128..159 of W1, i.e. the edge_attr block) lives in registers,
// packed along k (k-pairs) so the hot loop is pure FFMA2 + uniform LDG.128.
// msg = relu(pre_dst[dst] + pre_src[src] + ea @ W1c), then red.global.add.v4
// from even lanes only (16 REDG lanes per edge).
__global__ __launch_bounds__(256) void edge_kernel(
    const int* __restrict__ ei, const float* __restrict__ ea,
    const float* __restrict__ W1, int E) {
    const float* __restrict__ Wc = W1 + 128 * 64;
    const int lane = threadIdx.x & 31;
    const int c0 = 2 * lane;

    // wA[kp] = {Wc[2kp][c0],   Wc[2kp+1][c0]}
    // wB[kp] = {Wc[2kp][c0+1], Wc[2kp+1][c0+1]}
    unsigned long long wA[16], wB[16];
#pragma unroll
    for (int kp = 0; kp < 16; kp++) {
        wA[kp] = pack2(__ldg(Wc + (2 * kp) * 64 + c0),
                       __ldg(Wc + (2 * kp + 1) * 64 + c0));
        wB[kp] = pack2(__ldg(Wc + (2 * kp) * 64 + c0 + 1),
                       __ldg(Wc + (2 * kp + 1) * 64 + c0 + 1));
    }

    int warp = (blockIdx.x * blockDim.x + threadIdx.x) >> 5;
    int nw = (gridDim.x * blockDim.x) >> 5;

    for (int e = warp; e < E; e += nw) {
        const int src = __ldg(ei + e);
        const int dst = __ldg(ei + E + e);
        const ulonglong2* __restrict__ eap =
            reinterpret_cast<const ulonglong2*>(ea) + (size_t)e * 8;  // 32 floats/row

        unsigned long long accA = 0ull, accB = 0ull;
#pragma unroll
        for (int q = 0; q < 8; q++) {
            ulonglong2 ev = __ldg(eap + q);     // k-pairs 2q, 2q+1 (packed {ea[k],ea[k+1]})
            accA = fma2(ev.x, wA[2 * q], accA);
            accA = fma2(ev.y, wA[2 * q + 1], accA);
            accB = fma2(ev.x, wB[2 * q], accB);
            accB = fma2(ev.y, wB[2 * q + 1], accB);
        }

        float2 a2 = unpack2(accA);
        float2 b2 = unpack2(accB);
        float2 pd = __ldg(reinterpret_cast<const float2*>(g_pre_dst + (size_t)dst * 64) + lane);
        float2 ps = __ldg(reinterpret_cast<const float2*>(g_pre_src + (size_t)src * 64) + lane);
        float v0 = fmaxf(a2.x + a2.y + pd.x + ps.x, 0.f);   // col c0
        float v1 = fmaxf(b2.x + b2.y + pd.y + ps.y, 0.f);   // col c0+1

        // Swizzle: even lane picks up odd partner's two values -> 16-lane red.v4
        float w0 = __shfl_xor_sync(0xffffffffu, v0, 1);
        float w1 = __shfl_xor_sync(0xffffffffu, v1, 1);
        if (!(lane & 1)) {
            if ((v0 != 0.f) || (v1 != 0.f) || (w0 != 0.f) || (w1 != 0.f)) {
                float* ap = g_agg + (size_t)dst * 64 + c0;  // 16B aligned (c0 even*2)
                asm volatile("red.global.add.v4.f32 [%0], {%1, %2, %3, %4};"
                             :: "l"(ap), "f"(v0), "f"(v1), "f"(w0), "f"(w1)
                             : "memory");
            }
        }
    }
}

// ---------------- launch ------------------------------------------------------
extern "C" void kernel_launch(void* const* d_in, const int* in_sizes, int n_in,
                              void* d_out, int out_size) {
    const float* x     = (const float*)d_in[0];
    const int*   ei    = (const int*)d_in[1];
    const float* ea    = (const float*)d_in[2];
    const float* u     = (const float*)d_in[3];
    const int*   batch = (const int*)d_in[4];
    const float* W1    = (const float*)d_in[5];
    const float* b1    = (const float*)d_in[6];
    const float* W2    = (const float*)d_in[7];
    const float* b2    = (const float*)d_in[8];
    float* out = (float*)d_out;

    const int N = in_sizes[0] / 64;   // 100000
    const int E = in_sizes[2] / 32;   // 1000000

    float *pre_dst, *pre_src, *agg, *ugb, *uc2;
    cudaGetSymbolAddress((void**)&pre_dst, g_pre_dst);
    cudaGetSymbolAddress((void**)&pre_src, g_pre_src);
    cudaGetSymbolAddress((void**)&agg,     g_agg);
    cudaGetSymbolAddress((void**)&ugb,     g_ugb);
    cudaGetSymbolAddress((void**)&uc2,     g_uc2);

    // K0: per-graph tables
    glob_pre<<<1, dim3(64, 16)>>>(u, W1, b1, W2, b2);

    // zero the scatter target
    int n4 = N * 16;  // N*64/4 float4s
    zero_agg<<<(n4 + 255) / 256, 256>>>(n4);

    // pre_dst = x@W1[0:64]   + ugb[batch]   (bias folded into ugb)
    dense_gemm<<<(N + 63) / 64, 256>>>(x, nullptr, W1, ugb, batch, pre_dst, N, 1, 0);
    // pre_src = x@W1[64:128]
    dense_gemm<<<(N + 63) / 64, 256>>>(x, nullptr, W1 + 64 * 64, nullptr, nullptr, pre_src, N, 1, 0);

    // edge messages + scatter-sum
    edge_kernel<<<1184, 256>>>(ei, ea, W1, E);

    // out = relu(x@W2[0:64] + agg@W2[64:128] + uc2[batch])
    dense_gemm<<<(N + 63) / 64, 256>>>(x, agg, W2, uc2, batch, out, N, 2, 1);
}

// round 2
// speedup vs baseline: 1.0457x; 1.0457x over previous
#include <cuda_runtime.h>
#include <cstdint>

#define MAX_NODES 100000
#define D 64

// ---------------- scratch (device globals: no allocation allowed) ----------
__device__ float g_pre_dst[(size_t)MAX_NODES * D];  // x@W1a + (u@W1d + b1)[batch]
__device__ float g_pre_src[(size_t)MAX_NODES * D];  // x@W1b
__device__ float g_agg[(size_t)MAX_NODES * D];      // scatter-sum target
__device__ float g_ugb[16 * D];                     // u@W1d + b1 per graph
__device__ float g_uc2[16 * D];                     // u@W2c + b2 per graph

// ---------------- packed f32x2 helpers (Blackwell FFMA2) -------------------
__device__ __forceinline__ unsigned long long fma2(unsigned long long a,
                                                   unsigned long long b,
                                                   unsigned long long c) {
    unsigned long long d;
    asm("fma.rn.f32x2 %0, %1, %2, %3;" : "=l"(d) : "l"(a), "l"(b), "l"(c));
    return d;
}
__device__ __forceinline__ unsigned long long pack2(float x, float y) {
    unsigned long long r;
    asm("mov.b64 %0, {%1, %2};" : "=l"(r) : "f"(x), "f"(y));
    return r;
}
__device__ __forceinline__ float2 unpack2(unsigned long long v) {
    float2 r;
    asm("mov.b64 {%0, %1}, %2;" : "=f"(r.x), "=f"(r.y) : "l"(v));
    return r;
}

// ---------------- no-op (positions edge_kernel at ncu launch index 5) ------
__global__ void noop_k() {}

// ---------------- K0: per-graph precompute ---------------------------------
__global__ void glob_pre(const float* __restrict__ u,
                         const float* __restrict__ W1, const float* __restrict__ b1,
                         const float* __restrict__ W2, const float* __restrict__ b2) {
    int j = threadIdx.x;   // 0..63
    int g = threadIdx.y;   // 0..15
    float s1 = b1[j], s2 = b2[j];
#pragma unroll
    for (int k = 0; k < 32; k++) {
        float uv = u[g * 32 + k];
        s1 += uv * W1[(160 + k) * 64 + j];
        s2 += uv * W2[(128 + k) * 64 + j];
    }
    g_ugb[g * 64 + j] = s1;
    g_uc2[g * 64 + j] = s2;
}

// ---------------- zero agg --------------------------------------------------
__global__ void zero_agg(int n4) {
    int i = blockIdx.x * blockDim.x + threadIdx.x;
    if (i < n4) reinterpret_cast<float4*>(g_agg)[i] = make_float4(0.f, 0.f, 0.f, 0.f);
}

// ---------------- fused node pre-GEMM ---------------------------------------
// pre_dst[n] = x[n]@W1[0:64]  + ugb[batch[n]]
// pre_src[n] = x[n]@W1[64:128]
// One block = 64 nodes. sXT loaded ONCE, two weight passes.
__global__ __launch_bounds__(256) void node_pre(
    const float* __restrict__ x, const float* __restrict__ W1,
    const float* __restrict__ ugb, const int* __restrict__ batch, int N) {
    __shared__ float sXT[64][68];   // [k][node]
    __shared__ float sW[64][64];    // [k][col]
    const int tid = threadIdx.x;
    const int tn = tid & 15;
    const int tj = tid >> 4;
    const int node0 = blockIdx.x * 64;

    for (int i = tid; i < 4096; i += 256) {
        int r = i >> 6, c = i & 63;
        int n = node0 + r;
        sXT[c][r] = (n < N) ? x[(size_t)n * 64 + c] : 0.f;
    }

    unsigned long long acc[2][4][2];
#pragma unroll
    for (int a = 0; a < 2; a++)
#pragma unroll
        for (int i = 0; i < 4; i++) { acc[a][i][0] = 0ull; acc[a][i][1] = 0ull; }

    for (int a = 0; a < 2; a++) {
        __syncthreads();
        for (int i = tid; i < 4096; i += 256) {
            int k = i >> 6, j = i & 63;
            sW[k][j] = W1[(size_t)(a * 64 + k) * 64 + j];
        }
        __syncthreads();
#pragma unroll 8
        for (int k = 0; k < 64; k++) {
            float4 xv = *reinterpret_cast<const float4*>(&sXT[k][tn * 4]);
            ulonglong2 wv = *reinterpret_cast<const ulonglong2*>(&sW[k][tj * 4]);
            unsigned long long xd;
            xd = pack2(xv.x, xv.x);
            acc[a][0][0] = fma2(xd, wv.x, acc[a][0][0]); acc[a][0][1] = fma2(xd, wv.y, acc[a][0][1]);
            xd = pack2(xv.y, xv.y);
            acc[a][1][0] = fma2(xd, wv.x, acc[a][1][0]); acc[a][1][1] = fma2(xd, wv.y, acc[a][1][1]);
            xd = pack2(xv.z, xv.z);
            acc[a][2][0] = fma2(xd, wv.x, acc[a][2][0]); acc[a][2][1] = fma2(xd, wv.y, acc[a][2][1]);
            xd = pack2(xv.w, xv.w);
            acc[a][3][0] = fma2(xd, wv.x, acc[a][3][0]); acc[a][3][1] = fma2(xd, wv.y, acc[a][3][1]);
        }
    }

#pragma unroll
    for (int nn = 0; nn < 4; nn++) {
        int n = node0 + tn * 4 + nn;
        if (n < N) {
            // pre_dst (a=0) + ugb table
            float2 p0 = unpack2(acc[0][nn][0]);
            float2 p1 = unpack2(acc[0][nn][1]);
            int g = __ldg(batch + n);
            float4 tv = *reinterpret_cast<const float4*>(ugb + g * 64 + tj * 4);
            float4 o = make_float4(p0.x + tv.x, p0.y + tv.y, p1.x + tv.z, p1.y + tv.w);
            *reinterpret_cast<float4*>(g_pre_dst + (size_t)n * 64 + tj * 4) = o;
            // pre_src (a=1)
            p0 = unpack2(acc[1][nn][0]);
            p1 = unpack2(acc[1][nn][1]);
            float4 o2 = make_float4(p0.x, p0.y, p1.x, p1.y);
            *reinterpret_cast<float4*>(g_pre_src + (size_t)n * 64 + tj * 4) = o2;
        }
    }
}

// ---------------- final node GEMM --------------------------------------------
// out[n] = relu( x[n]@W2[0:64] + agg[n]@W2[64:128] + uc2[batch[n]] )
__global__ __launch_bounds__(256) void dense_final(
    const float* __restrict__ x, const float* __restrict__ W2,
    const float* __restrict__ uc2, const int* __restrict__ batch,
    float* __restrict__ out, int N) {
    __shared__ float sXT[64][68];
    __shared__ float sW[64][64];
    const int tid = threadIdx.x;
    const int tn = tid & 15;
    const int tj = tid >> 4;
    const int node0 = blockIdx.x * 64;

    unsigned long long acc[4][2];
#pragma unroll
    for (int i = 0; i < 4; i++) { acc[i][0] = 0ull; acc[i][1] = 0ull; }

    for (int a = 0; a < 2; a++) {
        const float* __restrict__ A = (a == 0) ? x : g_agg;
        for (int i = tid; i < 4096; i += 256) {
            int r = i >> 6, c = i & 63;
            int n = node0 + r;
            sXT[c][r] = (n < N) ? A[(size_t)n * 64 + c] : 0.f;
        }
        for (int i = tid; i < 4096; i += 256) {
            int k = i >> 6, j = i & 63;
            sW[k][j] = W2[(size_t)(a * 64 + k) * 64 + j];
        }
        __syncthreads();
#pragma unroll 8
        for (int k = 0; k < 64; k++) {
            float4 xv = *reinterpret_cast<const float4*>(&sXT[k][tn * 4]);
            ulonglong2 wv = *reinterpret_cast<const ulonglong2*>(&sW[k][tj * 4]);
            unsigned long long xd;
            xd = pack2(xv.x, xv.x);
            acc[0][0] = fma2(xd, wv.x, acc[0][0]); acc[0][1] = fma2(xd, wv.y, acc[0][1]);
            xd = pack2(xv.y, xv.y);
            acc[1][0] = fma2(xd, wv.x, acc[1][0]); acc[1][1] = fma2(xd, wv.y, acc[1][1]);
            xd = pack2(xv.z, xv.z);
            acc[2][0] = fma2(xd, wv.x, acc[2][0]); acc[2][1] = fma2(xd, wv.y, acc[2][1]);
            xd = pack2(xv.w, xv.w);
            acc[3][0] = fma2(xd, wv.x, acc[3][0]); acc[3][1] = fma2(xd, wv.y, acc[3][1]);
        }
        __syncthreads();
    }

#pragma unroll
    for (int nn = 0; nn < 4; nn++) {
        int n = node0 + tn * 4 + nn;
        if (n < N) {
            float2 p0 = unpack2(acc[nn][0]);
            float2 p1 = unpack2(acc[nn][1]);
            int g = __ldg(batch + n);
            float4 tv = *reinterpret_cast<const float4*>(uc2 + g * 64 + tj * 4);
            float4 o = make_float4(fmaxf(p0.x + tv.x, 0.f), fmaxf(p0.y + tv.y, 0.f),
                                   fmaxf(p1.x + tv.z, 0.f), fmaxf(p1.y + tv.w, 0.f));
            *reinterpret_cast<float4*>(out + (size_t)n * 64 + tj * 4) = o;
        }
    }
}

// ---------------- edge kernel ------------------------------------------------
// One warp per edge, software-pipelined: next edge's indices are fetched
// before this edge's gathers; all 8 ea loads issued back-to-back (MLP~10).
__global__ __launch_bounds__(256) void edge_kernel(
    const int* __restrict__ ei, const float* __restrict__ ea,
    const float* __restrict__ W1, int E) {
    const float* __restrict__ Wc = W1 + 128 * 64;
    const int lane = threadIdx.x & 31;
    const int c0 = 2 * lane;

    unsigned long long wA[16], wB[16];
#pragma unroll
    for (int kp = 0; kp < 16; kp++) {
        wA[kp] = pack2(__ldg(Wc + (2 * kp) * 64 + c0),
                       __ldg(Wc + (2 * kp + 1) * 64 + c0));
        wB[kp] = pack2(__ldg(Wc + (2 * kp) * 64 + c0 + 1),
                       __ldg(Wc + (2 * kp + 1) * 64 + c0 + 1));
    }

    const int warp = (blockIdx.x * blockDim.x + threadIdx.x) >> 5;
    const int nw = (gridDim.x * blockDim.x) >> 5;

    int e = warp;
    if (e >= E) return;
    int src = __ldg(ei + e);
    int dst = __ldg(ei + E + e);

    while (true) {
        // prefetch next edge's indices (L2 latency overlapped with this edge)
        const int en = e + nw;
        const bool more = (en < E);
        int srcn = 0, dstn = 0;
        if (more) { srcn = __ldg(ei + en); dstn = __ldg(ei + E + en); }

        // gathers for this edge (addresses already available)
        float2 pd = __ldg(reinterpret_cast<const float2*>(g_pre_dst + (size_t)dst * 64) + lane);
        float2 ps = __ldg(reinterpret_cast<const float2*>(g_pre_src + (size_t)src * 64) + lane);

        // all 8 independent ea loads up front
        const ulonglong2* __restrict__ eap =
            reinterpret_cast<const ulonglong2*>(ea) + (size_t)e * 8;
        ulonglong2 ev[8];
#pragma unroll
        for (int q = 0; q < 8; q++) ev[q] = __ldg(eap + q);

        unsigned long long accA = 0ull, accB = 0ull;
#pragma unroll
        for (int q = 0; q < 8; q++) {
            accA = fma2(ev[q].x, wA[2 * q], accA);
            accA = fma2(ev[q].y, wA[2 * q + 1], accA);
            accB = fma2(ev[q].x, wB[2 * q], accB);
            accB = fma2(ev[q].y, wB[2 * q + 1], accB);
        }

        float2 a2 = unpack2(accA);
        float2 b2 = unpack2(accB);
        float v0 = fmaxf(a2.x + a2.y + pd.x + ps.x, 0.f);
        float v1 = fmaxf(b2.x + b2.y + pd.y + ps.y, 0.f);

        float w0 = __shfl_xor_sync(0xffffffffu, v0, 1);
        float w1 = __shfl_xor_sync(0xffffffffu, v1, 1);
        if (!(lane & 1)) {
            if ((v0 != 0.f) || (v1 != 0.f) || (w0 != 0.f) || (w1 != 0.f)) {
                float* ap = g_agg + (size_t)dst * 64 + c0;
                asm volatile("red.global.add.v4.f32 [%0], {%1, %2, %3, %4};"
                             :: "l"(ap), "f"(v0), "f"(v1), "f"(w0), "f"(w1)
                             : "memory");
            }
        }

        if (!more) break;
        e = en; src = srcn; dst = dstn;
    }
}

// ---------------- launch ------------------------------------------------------
extern "C" void kernel_launch(void* const* d_in, const int* in_sizes, int n_in,
                              void* d_out, int out_size) {
    const float* x     = (const float*)d_in[0];
    const int*   ei    = (const int*)d_in[1];
    const float* ea    = (const float*)d_in[2];
    const float* u     = (const float*)d_in[3];
    const int*   batch = (const int*)d_in[4];
    const float* W1    = (const float*)d_in[5];
    const float* b1    = (const float*)d_in[6];
    const float* W2    = (const float*)d_in[7];
    const float* b2    = (const float*)d_in[8];
    float* out = (float*)d_out;

    const int N = in_sizes[0] / 64;   // 100000
    const int E = in_sizes[2] / 32;   // 1000000

    float *ugb, *uc2;
    cudaGetSymbolAddress((void**)&ugb, g_ugb);
    cudaGetSymbolAddress((void**)&uc2, g_uc2);

    // launch index 0
    glob_pre<<<1, dim3(64, 16)>>>(u, W1, b1, W2, b2);
    // launch index 1
    int n4 = N * 16;
    zero_agg<<<(n4 + 255) / 256, 256>>>(n4);
    // launch index 2: fused pre_dst + pre_src
    node_pre<<<(N + 63) / 64, 256>>>(x, W1, ugb, batch, N);
    // launch indices 3,4: no-ops so edge_kernel is launch #5 (ncu -s 5 -c 1)
    noop_k<<<1, 32>>>();
    noop_k<<<1, 32>>>();
    // launch index 5: edge messages + scatter-sum  <-- ncu captures this
    edge_kernel<<<1184, 256>>>(ei, ea, W1, E);
    // launch index 6: final node MLP
    dense_final<<<(N + 63) / 64, 256>>>(x, W2, uc2, batch, out, N);
}